// round 8
// baseline (speedup 1.0000x reference)
#include <cuda_runtime.h>
#include <cuda_fp16.h>
#include <cstdint>

// ---------------------------------------------------------------------------
// GAT layer. N=8192, IN_F=512, OUT_F=256.
// out = NEG * (colsum(h) - (adj>0) @ h),  h = x @ W, NEG = -9e15.
// R8: GAT GEMM 32x256 tile, full-K, no split-K; adj via cp.async (raw int32)
// + smem convert pass (no register staging -> no spills); direct epilogue.
// ---------------------------------------------------------------------------

#define NROWS   8192
#define IN_F    512
#define OUT_F   256
#define NEGC    (-9.0e15f)

// Static scratch
__device__ unsigned short g_Bh[(size_t)OUT_F * NROWS];   // h^T fp16 [k][j]
__device__ unsigned short g_W16[2 * OUT_F * IN_F];       // W^T fp16 limbs [limb][n][k]
__device__ float          g_Sp[64 * OUT_F];              // per-j-tile colsum partials
__device__ float          g_S[OUT_F];                    // colsum(h)

// ---------------------------------------------------------------------------
// helpers
// ---------------------------------------------------------------------------
__device__ __forceinline__ uint32_t smem_to_u32(const void* p) {
    uint32_t a;
    asm("{ .reg .u64 t; cvta.to.shared.u64 t, %1; cvt.u32.u64 %0, t; }" : "=r"(a) : "l"(p));
    return a;
}
__device__ __forceinline__ void cp_async16(uint32_t dst, const void* src) {
    asm volatile("cp.async.cg.shared.global [%0], [%1], 16;" :: "r"(dst), "l"(src));
}
__device__ __forceinline__ void cp_commit() { asm volatile("cp.async.commit_group;"); }
template <int N>
__device__ __forceinline__ void cp_wait() { asm volatile("cp.async.wait_group %0;" :: "n"(N)); }

__device__ __forceinline__ void ldsm_x4(uint32_t addr, uint32_t& r0, uint32_t& r1,
                                        uint32_t& r2, uint32_t& r3) {
    asm volatile("ldmatrix.sync.aligned.m8n8.x4.shared.b16 {%0,%1,%2,%3}, [%4];"
                 : "=r"(r0), "=r"(r1), "=r"(r2), "=r"(r3) : "r"(addr));
}
__device__ __forceinline__ void mma_f16(float* c, const uint32_t* a, uint32_t b0, uint32_t b1) {
    asm volatile("mma.sync.aligned.m16n8k16.row.col.f32.f16.f16.f32 "
                 "{%0,%1,%2,%3}, {%4,%5,%6,%7}, {%8,%9}, {%0,%1,%2,%3};"
                 : "+f"(c[0]), "+f"(c[1]), "+f"(c[2]), "+f"(c[3])
                 : "r"(a[0]), "r"(a[1]), "r"(a[2]), "r"(a[3]), "r"(b0), "r"(b1));
}
__device__ __forceinline__ uint32_t swz(uint32_t row, uint32_t col) {
    return row * 128u + (col ^ ((row & 7u) * 16u));
}
__device__ __forceinline__ uint32_t packh(float a, float b) {
    return (uint32_t)__half_as_ushort(__float2half_rn(a)) |
           ((uint32_t)__half_as_ushort(__float2half_rn(b)) << 16);
}

// ---------------------------------------------------------------------------
// Kernel A: split W into fp16 hi/lo limbs, transposed: g_W16[limb][n][k]
// ---------------------------------------------------------------------------
__global__ void __launch_bounds__(256) convert_W_kernel(const float* __restrict__ W) {
    int idx = blockIdx.x * 256 + threadIdx.x;       // 131072 total
    int n = idx & 255, k = idx >> 8;
    float v = W[(size_t)k * OUT_F + n];
    __half hi = __float2half_rn(v);
    __half lo = __float2half_rn(v - __half2float(hi));
    g_W16[n * IN_F + k] = __half_as_ushort(hi);
    g_W16[OUT_F * IN_F + n * IN_F + k] = __half_as_ushort(lo);
}

// ---------------------------------------------------------------------------
// Kernel B: h = x @ W on tensor cores, fp16 2-limb x 2-limb (3 terms).
// CTA: 128 j-rows x 128 n-cols, K=512 (8 chunks of 64). Grid (2 nt, 64 jt).
// Emits g_Bh[k][j] fp16 and g_Sp[jt][k] colsum partials.
// ---------------------------------------------------------------------------
#define HKC   64
#define H_A   (128 * HKC * 2)   // 16 KB per limb tile
#define H_STG (4 * H_A)         // Ahi|Alo|Bhi|Blo = 64 KB
#define H_SMEM (2 * H_STG)      // 128 KB

struct XReg { float4 v[8]; };

__device__ __forceinline__ void h_loadx(XReg& xr, const float* __restrict__ x,
                                        int j0, int it, int tid) {
    #pragma unroll
    for (int p = 0; p < 8; p++) {
        int lin = p * 256 + tid;
        int row = lin >> 4, c4 = lin & 15;
        xr.v[p] = *(const float4*)(x + (size_t)(j0 + row) * IN_F + it * HKC + c4 * 4);
    }
}
__device__ __forceinline__ void h_stsx(const XReg& xr, char* stg, int tid) {
    #pragma unroll
    for (int p = 0; p < 8; p++) {
        int lin = p * 256 + tid;
        int row = lin >> 4, c4 = lin & 15;
        float4 v = xr.v[p];
        __half hx = __float2half_rn(v.x), hy = __float2half_rn(v.y);
        __half hz = __float2half_rn(v.z), hw = __float2half_rn(v.w);
        uint32_t o = swz((uint32_t)row, (uint32_t)(c4 * 8));
        *(uint2*)(stg + o) = make_uint2(
            (uint32_t)__half_as_ushort(hx) | ((uint32_t)__half_as_ushort(hy) << 16),
            (uint32_t)__half_as_ushort(hz) | ((uint32_t)__half_as_ushort(hw) << 16));
        *(uint2*)(stg + H_A + o) = make_uint2(
            packh(v.x - __half2float(hx), v.y - __half2float(hy)),
            packh(v.z - __half2float(hz), v.w - __half2float(hw)));
    }
}
__device__ __forceinline__ void h_cpB(uint32_t stg, int n0, int it, int tid) {
    #pragma unroll
    for (int limb = 0; limb < 2; limb++) {
        #pragma unroll
        for (int p = 0; p < 4; p++) {
            int lin = p * 256 + tid;
            int row = lin >> 3, cx = lin & 7;
            const void* src = g_W16 + (size_t)limb * OUT_F * IN_F +
                              (size_t)(n0 + row) * IN_F + it * HKC + cx * 8;
            cp_async16(stg + 2 * H_A + limb * H_A + swz((uint32_t)row, (uint32_t)(cx * 16)), src);
        }
    }
}

__global__ void __launch_bounds__(256, 1) gemm_h_kernel(const float* __restrict__ x) {
    extern __shared__ char sm[];
    uint32_t smb = smem_to_u32(sm);
    int tid = threadIdx.x;
    int l = tid & 31, w = tid >> 5;
    int mw = w & 3, nw = w >> 2;          // 4 x 2 warps, warp tile 32x64
    int n0 = blockIdx.x * 128;
    int j0 = blockIdx.y * 128;
    int jt = blockIdx.y;

    int g = l >> 3, lr = l & 7;
    uint32_t a_row0 = (uint32_t)(mw * 32 + (g & 1) * 8 + lr);
    uint32_t a_kb   = (uint32_t)((g >> 1) * 16);
    uint32_t b_row0 = (uint32_t)(nw * 64 + (g >> 1) * 8 + lr);
    uint32_t b_kb   = (uint32_t)((g & 1) * 16);

    float acc[2][8][4];
    #pragma unroll
    for (int mf = 0; mf < 2; mf++)
        #pragma unroll
        for (int nf = 0; nf < 8; nf++)
            #pragma unroll
            for (int q = 0; q < 4; q++) acc[mf][nf][q] = 0.0f;

    XReg xr;
    h_loadx(xr, x, j0, 0, tid);
    h_stsx(xr, sm, tid);
    h_cpB(smb, n0, 0, tid);
    cp_commit();
    h_loadx(xr, x, j0, 1, tid);

    for (int it = 0; it < 8; ++it) {
        cp_wait<0>();
        __syncthreads();
        if (it + 1 < 8) {
            char* stg = sm + ((it + 1) & 1) * H_STG;
            h_stsx(xr, stg, tid);
            h_cpB(smb + ((it + 1) & 1) * H_STG, n0, it + 1, tid);
            cp_commit();
            if (it + 2 < 8) h_loadx(xr, x, j0, it + 2, tid);
        }
        uint32_t Sb = smb + (it & 1) * H_STG;
        #pragma unroll
        for (int ks = 0; ks < 4; ks++) {
            uint32_t afh[2][4], afl[2][4];
            #pragma unroll
            for (int mf = 0; mf < 2; mf++) {
                uint32_t o = swz(a_row0 + mf * 16u, (uint32_t)(ks * 32) + a_kb);
                ldsm_x4(Sb + o, afh[mf][0], afh[mf][1], afh[mf][2], afh[mf][3]);
                ldsm_x4(Sb + H_A + o, afl[mf][0], afl[mf][1], afl[mf][2], afl[mf][3]);
            }
            #pragma unroll
            for (int nf2 = 0; nf2 < 4; nf2++) {
                uint32_t o = swz(b_row0 + nf2 * 16u, (uint32_t)(ks * 32) + b_kb);
                uint32_t h0, h1, h2, h3, l0, l1, l2, l3;
                ldsm_x4(Sb + 2 * H_A + o, h0, h1, h2, h3);
                ldsm_x4(Sb + 3 * H_A + o, l0, l1, l2, l3);
                #pragma unroll
                for (int mf = 0; mf < 2; mf++) {
                    mma_f16(acc[mf][nf2 * 2 + 0], afh[mf], h0, h1);
                    mma_f16(acc[mf][nf2 * 2 + 1], afh[mf], h2, h3);
                    mma_f16(acc[mf][nf2 * 2 + 0], afl[mf], h0, h1);
                    mma_f16(acc[mf][nf2 * 2 + 1], afl[mf], h2, h3);
                    mma_f16(acc[mf][nf2 * 2 + 0], afh[mf], l0, l1);
                    mma_f16(acc[mf][nf2 * 2 + 1], afh[mf], l2, l3);
                }
            }
        }
    }

    // epilogue: stage h (fp16) into smem [j][k], pitch 130 halves
    __syncthreads();
    unsigned short* hbuf = (unsigned short*)sm;
    const int P = 130;
    #pragma unroll
    for (int mf = 0; mf < 2; mf++) {
        int r = mw * 32 + mf * 16 + (l >> 2);
        #pragma unroll
        for (int nf = 0; nf < 8; nf++) {
            int c = nw * 64 + nf * 8 + (l & 3) * 2;
            *(uint32_t*)&hbuf[r * P + c] = packh(acc[mf][nf][0], acc[mf][nf][1]);
            *(uint32_t*)&hbuf[(r + 8) * P + c] = packh(acc[mf][nf][2], acc[mf][nf][3]);
        }
    }
    __syncthreads();

    // colsum partials
    if (tid < 128) {
        float s = 0.0f;
        #pragma unroll 8
        for (int j = 0; j < 128; j++)
            s += __half2float(__ushort_as_half(hbuf[j * P + tid]));
        g_Sp[jt * OUT_F + n0 + tid] = s;
    }

    // transposed write: g_Bh[n0+kl][j0 .. j0+127]
    {
        int kl = tid >> 1, jh = (tid & 1) * 64;
        unsigned short* dst = g_Bh + (size_t)(n0 + kl) * NROWS + j0 + jh;
        #pragma unroll
        for (int q = 0; q < 8; q++) {
            uint32_t u[4];
            #pragma unroll
            for (int e = 0; e < 4; e++) {
                unsigned short v0 = hbuf[(jh + q * 8 + e * 2 + 0) * P + kl];
                unsigned short v1 = hbuf[(jh + q * 8 + e * 2 + 1) * P + kl];
                u[e] = (uint32_t)v0 | ((uint32_t)v1 << 16);
            }
            *(uint4*)(dst + q * 8) = make_uint4(u[0], u[1], u[2], u[3]);
        }
    }
}

// ---------------------------------------------------------------------------
// Kernel C: reduce colsum partials
// ---------------------------------------------------------------------------
__global__ void reduce_S_kernel() {
    int c = threadIdx.x;
    float s = 0.0f;
    #pragma unroll 8
    for (int jt = 0; jt < 64; jt++) s += g_Sp[jt * OUT_F + c];
    g_S[c] = s;
}

// ---------------------------------------------------------------------------
// Kernel D: masked GEMM (adj>0) @ h, fp16 mma.sync, full K per CTA.
// CTA: 32 rows x 256 cols x K=8192 (128 chunks of 64). Grid 256 CTAs.
// adj staged raw (cp.async int32, 2 stages) -> smem convert pass -> fp16 A
// (2 stages); B (g_Bh panel) 2 stages. ONE sync + one cp group per chunk.
// 8 warps = 2mw x 4nw, warp tile 16x64, acc=32 regs. Direct epilogue.
// ---------------------------------------------------------------------------
#define KC      64
#define AI_ST   (32 * KC * 4)             // 8 KB (raw int32)
#define AF_ST   (32 * KC * 2)             // 4 KB (fp16)
#define B_ST    (256 * KC * 2)            // 32 KB
#define AI_BASE 0
#define AF_BASE (2 * AI_ST)               // 16 KB
#define B_BASE  (AF_BASE + 2 * AF_ST)     // 24 KB
#define SS_BASE (B_BASE + 2 * B_ST)       // 88 KB
#define GAT_SMEM (SS_BASE + 1024)         // 89 KB

__device__ __forceinline__ void g_cpAi(uint32_t smaddr, const int* __restrict__ adj,
                                       int m0, int it, int tid) {
    // 32 rows x 64 int32 = 8KB; thread: 32B linear
    int row = tid >> 3, c8 = (tid & 7) * 8;
    const int* src = adj + (size_t)(m0 + row) * NROWS + it * KC + c8;
    uint32_t dst = smaddr + (uint32_t)tid * 32u;
    cp_async16(dst, src);
    cp_async16(dst + 16, src + 4);
}
__device__ __forceinline__ void g_convA(const char* ai, char* af, int tid) {
    // thread: 8 int32 -> 8 fp16 (16B), swizzled store
    int row = tid >> 3;
    const int4* s = (const int4*)(ai + tid * 32);
    int4 a = s[0], b = s[1];
    uint32_t u0 = (uint32_t)(a.x + (a.y << 16)) * 0x3C00u;
    uint32_t u1 = (uint32_t)(a.z + (a.w << 16)) * 0x3C00u;
    uint32_t u2 = (uint32_t)(b.x + (b.y << 16)) * 0x3C00u;
    uint32_t u3 = (uint32_t)(b.z + (b.w << 16)) * 0x3C00u;
    *(uint4*)(af + swz((uint32_t)row, (uint32_t)((tid & 7) * 16))) =
        make_uint4(u0, u1, u2, u3);
}
__device__ __forceinline__ void g_cpB(uint32_t smaddr, int it, int tid) {
    size_t kk = (size_t)it * KC;
    #pragma unroll
    for (int p = 0; p < 8; p++) {
        int lin = p * 256 + tid;
        int row = lin >> 3, cx = lin & 7;
        const void* src = g_Bh + (size_t)row * NROWS + kk + cx * 8;
        cp_async16(smaddr + swz((uint32_t)row, (uint32_t)(cx * 16)), src);
    }
}

__global__ void __launch_bounds__(256, 2) gat_gemm_kernel(const int* __restrict__ adj,
                                                          float* __restrict__ out) {
    extern __shared__ char sm[];
    uint32_t smb = smem_to_u32(sm);
    float* sS = (float*)(sm + SS_BASE);
    int tid = threadIdx.x;
    int l = tid & 31, w = tid >> 5;
    int mw = w & 1, nw = w >> 1;          // 2 x 4 warps, warp tile 16x64
    int m0 = blockIdx.x * 32;

    int g = l >> 3, lr = l & 7;
    uint32_t a_row0 = (uint32_t)(mw * 16 + (g & 1) * 8 + lr);
    uint32_t a_kb   = (uint32_t)((g >> 1) * 16);
    uint32_t b_row0 = (uint32_t)(nw * 64 + (g >> 1) * 8 + lr);
    uint32_t b_kb   = (uint32_t)((g & 1) * 16);

    float acc[8][4];
    #pragma unroll
    for (int nf = 0; nf < 8; nf++)
        #pragma unroll
        for (int q = 0; q < 4; q++) acc[nf][q] = 0.0f;

    // prologue
    g_cpAi(smb + AI_BASE, adj, m0, 0, tid);
    cp_commit();                                   // group: Ai(0)
    g_cpB(smb + B_BASE, 0, tid);
    g_cpAi(smb + AI_BASE + AI_ST, adj, m0, 1, tid);
    cp_commit();                                   // group: B(0), Ai(1)
    sS[tid] = g_S[tid];
    cp_wait<1>();                                  // Ai(0) done
    __syncthreads();
    g_convA(sm + AI_BASE, sm + AF_BASE, tid);      // Af(0)

    const int NCHUNK = NROWS / KC; // 128
    for (int it = 0; it < NCHUNK; ++it) {
        cp_wait<0>();                              // B(it), Ai(it+1) done
        __syncthreads();                           // Af(it) visible to all

        if (it + 1 < NCHUNK) {
            g_convA(sm + AI_BASE + ((it + 1) & 1) * AI_ST,
                    sm + AF_BASE + ((it + 1) & 1) * AF_ST, tid);
            g_cpB(smb + B_BASE + ((it + 1) & 1) * B_ST, it + 1, tid);
            if (it + 2 < NCHUNK)
                g_cpAi(smb + AI_BASE + ((it + 2) & 1) * AI_ST, adj, m0, it + 2, tid);
            cp_commit();
        }

        uint32_t Ab = smb + AF_BASE + (it & 1) * AF_ST;
        uint32_t Bb = smb + B_BASE + (it & 1) * B_ST;
        #pragma unroll
        for (int ks = 0; ks < 4; ks++) {
            uint32_t af[4];
            {
                uint32_t o = swz(a_row0, (uint32_t)(ks * 32) + a_kb);
                ldsm_x4(Ab + o, af[0], af[1], af[2], af[3]);
            }
            #pragma unroll
            for (int nf2 = 0; nf2 < 4; nf2++) {
                uint32_t r0, r1, r2, r3;
                uint32_t o = swz(b_row0 + nf2 * 16u, (uint32_t)(ks * 32) + b_kb);
                ldsm_x4(Bb + o, r0, r1, r2, r3);
                mma_f16(acc[nf2 * 2 + 0], af, r0, r1);
                mma_f16(acc[nf2 * 2 + 1], af, r2, r3);
            }
        }
    }

    // epilogue: out = NEG * (S - acc), direct
    int r0 = m0 + mw * 16 + (l >> 2);
    #pragma unroll
    for (int nf = 0; nf < 8; nf++) {
        int col = nw * 64 + nf * 8 + (l & 3) * 2;
        float s0 = sS[col], s1 = sS[col + 1];
        *(float2*)(out + (size_t)r0 * OUT_F + col) =
            make_float2(NEGC * (s0 - acc[nf][0]), NEGC * (s1 - acc[nf][1]));
        *(float2*)(out + (size_t)(r0 + 8) * OUT_F + col) =
            make_float2(NEGC * (s0 - acc[nf][2]), NEGC * (s1 - acc[nf][3]));
    }
}

// ---------------------------------------------------------------------------
// Launch
// ---------------------------------------------------------------------------
extern "C" void kernel_launch(void* const* d_in, const int* in_sizes, int n_in,
                              void* d_out, int out_size) {
    const float* x   = (const float*)d_in[0];   // [8192, 512]
    const float* W   = (const float*)d_in[1];   // [512, 256]
    const int*   adj = (const int*)d_in[3];     // [8192, 8192]
    float* out = (float*)d_out;                 // [8192, 256]

    convert_W_kernel<<<512, 256>>>(W);

    cudaFuncSetAttribute(gemm_h_kernel, cudaFuncAttributeMaxDynamicSharedMemorySize, H_SMEM);
    gemm_h_kernel<<<dim3(2, 64), 256, H_SMEM>>>(x);

    reduce_S_kernel<<<1, 256>>>();

    cudaFuncSetAttribute(gat_gemm_kernel, cudaFuncAttributeMaxDynamicSharedMemorySize, GAT_SMEM);
    gat_gemm_kernel<<<NROWS / 32, 256, GAT_SMEM>>>(adj, out);
}

// round 11
// speedup vs baseline: 1.0002x; 1.0002x over previous
#include <cuda_runtime.h>
#include <cuda_fp16.h>
#include <cstdint>

// ---------------------------------------------------------------------------
// GAT layer. N=8192, IN_F=512, OUT_F=256.
// out = NEG * (colsum(h) - (adj>0) @ h),  h = x @ W, NEG = -9e15.
// R9: R7 tile shape (64x256, split-K 2, warp 32x64) + R8 smem-staged adj
// convert (no register staging -> no spills). 5 launches.
// ---------------------------------------------------------------------------

#define NROWS   8192
#define IN_F    512
#define OUT_F   256
#define NEGC    (-9.0e15f)

// Static scratch
__device__ unsigned short g_Bh[(size_t)OUT_F * NROWS];   // h^T fp16 [k][j]
__device__ unsigned short g_W16[2 * OUT_F * IN_F];       // W^T fp16 limbs [limb][n][k]
__device__ float          g_Sp[64 * OUT_F];              // per-j-tile colsum partials
__device__ float          g_S[OUT_F];                    // colsum(h)
__device__ float          g_P[2 * (size_t)NROWS * OUT_F];// split-K partials

// ---------------------------------------------------------------------------
// helpers
// ---------------------------------------------------------------------------
__device__ __forceinline__ uint32_t smem_to_u32(const void* p) {
    uint32_t a;
    asm("{ .reg .u64 t; cvta.to.shared.u64 t, %1; cvt.u32.u64 %0, t; }" : "=r"(a) : "l"(p));
    return a;
}
__device__ __forceinline__ void cp_async16(uint32_t dst, const void* src) {
    asm volatile("cp.async.cg.shared.global [%0], [%1], 16;" :: "r"(dst), "l"(src));
}
__device__ __forceinline__ void cp_commit() { asm volatile("cp.async.commit_group;"); }
template <int N>
__device__ __forceinline__ void cp_wait() { asm volatile("cp.async.wait_group %0;" :: "n"(N)); }

__device__ __forceinline__ void ldsm_x4(uint32_t addr, uint32_t& r0, uint32_t& r1,
                                        uint32_t& r2, uint32_t& r3) {
    asm volatile("ldmatrix.sync.aligned.m8n8.x4.shared.b16 {%0,%1,%2,%3}, [%4];"
                 : "=r"(r0), "=r"(r1), "=r"(r2), "=r"(r3) : "r"(addr));
}
__device__ __forceinline__ void mma_f16(float* c, const uint32_t* a, uint32_t b0, uint32_t b1) {
    asm volatile("mma.sync.aligned.m16n8k16.row.col.f32.f16.f16.f32 "
                 "{%0,%1,%2,%3}, {%4,%5,%6,%7}, {%8,%9}, {%0,%1,%2,%3};"
                 : "+f"(c[0]), "+f"(c[1]), "+f"(c[2]), "+f"(c[3])
                 : "r"(a[0]), "r"(a[1]), "r"(a[2]), "r"(a[3]), "r"(b0), "r"(b1));
}
__device__ __forceinline__ uint32_t swz(uint32_t row, uint32_t col) {
    return row * 128u + (col ^ ((row & 7u) * 16u));
}
__device__ __forceinline__ uint32_t packh(float a, float b) {
    return (uint32_t)__half_as_ushort(__float2half_rn(a)) |
           ((uint32_t)__half_as_ushort(__float2half_rn(b)) << 16);
}

// ---------------------------------------------------------------------------
// Kernel A: split W into fp16 hi/lo limbs, transposed: g_W16[limb][n][k]
// ---------------------------------------------------------------------------
__global__ void __launch_bounds__(256) convert_W_kernel(const float* __restrict__ W) {
    int idx = blockIdx.x * 256 + threadIdx.x;       // 131072 total
    int n = idx & 255, k = idx >> 8;
    float v = W[(size_t)k * OUT_F + n];
    __half hi = __float2half_rn(v);
    __half lo = __float2half_rn(v - __half2float(hi));
    g_W16[n * IN_F + k] = __half_as_ushort(hi);
    g_W16[OUT_F * IN_F + n * IN_F + k] = __half_as_ushort(lo);
}

// ---------------------------------------------------------------------------
// Kernel B: h = x @ W on tensor cores, fp16 2-limb x 2-limb (3 terms).
// CTA: 128 j-rows x 128 n-cols, K=512 (8 chunks of 64). Grid (2 nt, 64 jt).
// Emits g_Bh[k][j] fp16 and g_Sp[jt][k] colsum partials.
// ---------------------------------------------------------------------------
#define HKC   64
#define H_A   (128 * HKC * 2)   // 16 KB per limb tile
#define H_STG (4 * H_A)         // Ahi|Alo|Bhi|Blo = 64 KB
#define H_SMEM (2 * H_STG)      // 128 KB

struct XReg { float4 v[8]; };

__device__ __forceinline__ void h_loadx(XReg& xr, const float* __restrict__ x,
                                        int j0, int it, int tid) {
    #pragma unroll
    for (int p = 0; p < 8; p++) {
        int lin = p * 256 + tid;
        int row = lin >> 4, c4 = lin & 15;
        xr.v[p] = *(const float4*)(x + (size_t)(j0 + row) * IN_F + it * HKC + c4 * 4);
    }
}
__device__ __forceinline__ void h_stsx(const XReg& xr, char* stg, int tid) {
    #pragma unroll
    for (int p = 0; p < 8; p++) {
        int lin = p * 256 + tid;
        int row = lin >> 4, c4 = lin & 15;
        float4 v = xr.v[p];
        __half hx = __float2half_rn(v.x), hy = __float2half_rn(v.y);
        __half hz = __float2half_rn(v.z), hw = __float2half_rn(v.w);
        uint32_t o = swz((uint32_t)row, (uint32_t)(c4 * 8));
        *(uint2*)(stg + o) = make_uint2(
            (uint32_t)__half_as_ushort(hx) | ((uint32_t)__half_as_ushort(hy) << 16),
            (uint32_t)__half_as_ushort(hz) | ((uint32_t)__half_as_ushort(hw) << 16));
        *(uint2*)(stg + H_A + o) = make_uint2(
            packh(v.x - __half2float(hx), v.y - __half2float(hy)),
            packh(v.z - __half2float(hz), v.w - __half2float(hw)));
    }
}
__device__ __forceinline__ void h_cpB(uint32_t stg, int n0, int it, int tid) {
    #pragma unroll
    for (int limb = 0; limb < 2; limb++) {
        #pragma unroll
        for (int p = 0; p < 4; p++) {
            int lin = p * 256 + tid;
            int row = lin >> 3, cx = lin & 7;
            const void* src = g_W16 + (size_t)limb * OUT_F * IN_F +
                              (size_t)(n0 + row) * IN_F + it * HKC + cx * 8;
            cp_async16(stg + 2 * H_A + limb * H_A + swz((uint32_t)row, (uint32_t)(cx * 16)), src);
        }
    }
}

__global__ void __launch_bounds__(256, 1) gemm_h_kernel(const float* __restrict__ x) {
    extern __shared__ char sm[];
    uint32_t smb = smem_to_u32(sm);
    int tid = threadIdx.x;
    int l = tid & 31, w = tid >> 5;
    int mw = w & 3, nw = w >> 2;          // 4 x 2 warps, warp tile 32x64
    int n0 = blockIdx.x * 128;
    int j0 = blockIdx.y * 128;
    int jt = blockIdx.y;

    int g = l >> 3, lr = l & 7;
    uint32_t a_row0 = (uint32_t)(mw * 32 + (g & 1) * 8 + lr);
    uint32_t a_kb   = (uint32_t)((g >> 1) * 16);
    uint32_t b_row0 = (uint32_t)(nw * 64 + (g >> 1) * 8 + lr);
    uint32_t b_kb   = (uint32_t)((g & 1) * 16);

    float acc[2][8][4];
    #pragma unroll
    for (int mf = 0; mf < 2; mf++)
        #pragma unroll
        for (int nf = 0; nf < 8; nf++)
            #pragma unroll
            for (int q = 0; q < 4; q++) acc[mf][nf][q] = 0.0f;

    XReg xr;
    h_loadx(xr, x, j0, 0, tid);
    h_stsx(xr, sm, tid);
    h_cpB(smb, n0, 0, tid);
    cp_commit();
    h_loadx(xr, x, j0, 1, tid);

    for (int it = 0; it < 8; ++it) {
        cp_wait<0>();
        __syncthreads();
        if (it + 1 < 8) {
            char* stg = sm + ((it + 1) & 1) * H_STG;
            h_stsx(xr, stg, tid);
            h_cpB(smb + ((it + 1) & 1) * H_STG, n0, it + 1, tid);
            cp_commit();
            if (it + 2 < 8) h_loadx(xr, x, j0, it + 2, tid);
        }
        uint32_t Sb = smb + (it & 1) * H_STG;
        #pragma unroll
        for (int ks = 0; ks < 4; ks++) {
            uint32_t afh[2][4], afl[2][4];
            #pragma unroll
            for (int mf = 0; mf < 2; mf++) {
                uint32_t o = swz(a_row0 + mf * 16u, (uint32_t)(ks * 32) + a_kb);
                ldsm_x4(Sb + o, afh[mf][0], afh[mf][1], afh[mf][2], afh[mf][3]);
                ldsm_x4(Sb + H_A + o, afl[mf][0], afl[mf][1], afl[mf][2], afl[mf][3]);
            }
            #pragma unroll
            for (int nf2 = 0; nf2 < 4; nf2++) {
                uint32_t o = swz(b_row0 + nf2 * 16u, (uint32_t)(ks * 32) + b_kb);
                uint32_t h0, h1, h2, h3, l0, l1, l2, l3;
                ldsm_x4(Sb + 2 * H_A + o, h0, h1, h2, h3);
                ldsm_x4(Sb + 3 * H_A + o, l0, l1, l2, l3);
                #pragma unroll
                for (int mf = 0; mf < 2; mf++) {
                    mma_f16(acc[mf][nf2 * 2 + 0], afh[mf], h0, h1);
                    mma_f16(acc[mf][nf2 * 2 + 1], afh[mf], h2, h3);
                    mma_f16(acc[mf][nf2 * 2 + 0], afl[mf], h0, h1);
                    mma_f16(acc[mf][nf2 * 2 + 1], afl[mf], h2, h3);
                    mma_f16(acc[mf][nf2 * 2 + 0], afh[mf], l0, l1);
                    mma_f16(acc[mf][nf2 * 2 + 1], afh[mf], l2, l3);
                }
            }
        }
    }

    // epilogue: stage h (fp16) into smem [j][k], pitch 130 halves
    __syncthreads();
    unsigned short* hbuf = (unsigned short*)sm;
    const int P = 130;
    #pragma unroll
    for (int mf = 0; mf < 2; mf++) {
        int r = mw * 32 + mf * 16 + (l >> 2);
        #pragma unroll
        for (int nf = 0; nf < 8; nf++) {
            int c = nw * 64 + nf * 8 + (l & 3) * 2;
            *(uint32_t*)&hbuf[r * P + c] = packh(acc[mf][nf][0], acc[mf][nf][1]);
            *(uint32_t*)&hbuf[(r + 8) * P + c] = packh(acc[mf][nf][2], acc[mf][nf][3]);
        }
    }
    __syncthreads();

    // colsum partials
    if (tid < 128) {
        float s = 0.0f;
        #pragma unroll 8
        for (int j = 0; j < 128; j++)
            s += __half2float(__ushort_as_half(hbuf[j * P + tid]));
        g_Sp[jt * OUT_F + n0 + tid] = s;
    }

    // transposed write: g_Bh[n0+kl][j0 .. j0+127]
    {
        int kl = tid >> 1, jh = (tid & 1) * 64;
        unsigned short* dst = g_Bh + (size_t)(n0 + kl) * NROWS + j0 + jh;
        #pragma unroll
        for (int q = 0; q < 8; q++) {
            uint32_t u[4];
            #pragma unroll
            for (int e = 0; e < 4; e++) {
                unsigned short v0 = hbuf[(jh + q * 8 + e * 2 + 0) * P + kl];
                unsigned short v1 = hbuf[(jh + q * 8 + e * 2 + 1) * P + kl];
                u[e] = (uint32_t)v0 | ((uint32_t)v1 << 16);
            }
            *(uint4*)(dst + q * 8) = make_uint4(u[0], u[1], u[2], u[3]);
        }
    }
}

// ---------------------------------------------------------------------------
// Kernel C: reduce colsum partials
// ---------------------------------------------------------------------------
__global__ void reduce_S_kernel() {
    int c = threadIdx.x;
    float s = 0.0f;
    #pragma unroll 8
    for (int jt = 0; jt < 64; jt++) s += g_Sp[jt * OUT_F + c];
    g_S[c] = s;
}

// ---------------------------------------------------------------------------
// Kernel D: masked GEMM (adj>0) @ h, split-K(2), fp16 mma.sync.
// CTA: 64 rows x 256 cols x K=4096 (64 chunks of 64). Grid (2 kt, 128 mt).
// adj staged raw via cp.async (2 stages, 16KB) -> smem convert -> fp16 A
// (2 stages, 8KB); B 2 stages (64KB). 112KB total -> 2 CTAs/SM.
// 8 warps = 2mw x 4nw, warp tile 32x64 (0.375 ldsm/mma). No reg staging.
// ---------------------------------------------------------------------------
#define KC      64
#define AI_ST   (64 * KC * 4)             // 16 KB raw int32
#define AF_ST   (64 * KC * 2)             // 8 KB fp16
#define B_ST    (256 * KC * 2)            // 32 KB
#define AI_BASE 0
#define AF_BASE (2 * AI_ST)               // 32 KB
#define B_BASE  (AF_BASE + 2 * AF_ST)     // 48 KB
#define GAT_SMEM (B_BASE + 2 * B_ST)      // 112 KB

__device__ __forceinline__ void g_cpAi(uint32_t smaddr, const int* __restrict__ adj,
                                       int m0, int k0, int it, int tid) {
    // 64 rows x 64 int32 = 16 KB; thread: 64 B linear
    int row = tid >> 2, c16 = (tid & 3) * 16;
    const int* src = adj + (size_t)(m0 + row) * NROWS + k0 + it * KC + c16;
    uint32_t dst = smaddr + (uint32_t)tid * 64u;
    cp_async16(dst, src);
    cp_async16(dst + 16, src + 4);
    cp_async16(dst + 32, src + 8);
    cp_async16(dst + 48, src + 12);
}
__device__ __forceinline__ void g_convA(const char* ai, char* af, int tid) {
    // thread: 16 int32 -> 16 fp16 (32 B), swizzled store
    int row = tid >> 2;
    const int4* s = (const int4*)(ai + tid * 64);
    int4 a = s[0], b = s[1], c = s[2], d = s[3];
    uint32_t u0 = (uint32_t)(a.x + (a.y << 16)) * 0x3C00u;
    uint32_t u1 = (uint32_t)(a.z + (a.w << 16)) * 0x3C00u;
    uint32_t u2 = (uint32_t)(b.x + (b.y << 16)) * 0x3C00u;
    uint32_t u3 = (uint32_t)(b.z + (b.w << 16)) * 0x3C00u;
    uint32_t u4 = (uint32_t)(c.x + (c.y << 16)) * 0x3C00u;
    uint32_t u5 = (uint32_t)(c.z + (c.w << 16)) * 0x3C00u;
    uint32_t u6 = (uint32_t)(d.x + (d.y << 16)) * 0x3C00u;
    uint32_t u7 = (uint32_t)(d.z + (d.w << 16)) * 0x3C00u;
    uint32_t base = (uint32_t)((tid & 3) * 32);
    *(uint4*)(af + swz((uint32_t)row, base)) = make_uint4(u0, u1, u2, u3);
    *(uint4*)(af + swz((uint32_t)row, base + 16)) = make_uint4(u4, u5, u6, u7);
}
__device__ __forceinline__ void g_cpB(uint32_t smaddr, int k0, int it, int tid) {
    size_t kk = (size_t)k0 + it * KC;
    #pragma unroll
    for (int p = 0; p < 8; p++) {
        int lin = p * 256 + tid;
        int row = lin >> 3, cx = lin & 7;
        const void* src = g_Bh + (size_t)row * NROWS + kk + cx * 8;
        cp_async16(smaddr + swz((uint32_t)row, (uint32_t)(cx * 16)), src);
    }
}

__global__ void __launch_bounds__(256, 2) gat_gemm_kernel(const int* __restrict__ adj) {
    extern __shared__ char sm[];
    uint32_t smb = smem_to_u32(sm);
    int tid = threadIdx.x;
    int l = tid & 31, w = tid >> 5;
    int mw = w & 1, nw = w >> 1;          // 2 x 4 warps, warp tile 32x64
    int kt = blockIdx.x;                  // split-K half
    int m0 = blockIdx.y * 64;
    int k0 = kt * (NROWS / 2);

    int g = l >> 3, lr = l & 7;
    uint32_t a_row0 = (uint32_t)(mw * 32 + (g & 1) * 8 + lr);
    uint32_t a_kb   = (uint32_t)((g >> 1) * 16);
    uint32_t b_row0 = (uint32_t)(nw * 64 + (g >> 1) * 8 + lr);
    uint32_t b_kb   = (uint32_t)((g & 1) * 16);

    float acc[2][8][4];
    #pragma unroll
    for (int mf = 0; mf < 2; mf++)
        #pragma unroll
        for (int nf = 0; nf < 8; nf++)
            #pragma unroll
            for (int q = 0; q < 4; q++) acc[mf][nf][q] = 0.0f;

    // prologue
    g_cpAi(smb + AI_BASE, adj, m0, k0, 0, tid);
    cp_commit();                                   // group: Ai(0)
    g_cpB(smb + B_BASE, k0, 0, tid);
    g_cpAi(smb + AI_BASE + AI_ST, adj, m0, k0, 1, tid);
    cp_commit();                                   // group: B(0), Ai(1)
    cp_wait<1>();                                  // Ai(0) done
    __syncthreads();
    g_convA(sm + AI_BASE, sm + AF_BASE, tid);      // Af(0)

    const int NCHUNK = (NROWS / 2) / KC;           // 64
    for (int it = 0; it < NCHUNK; ++it) {
        cp_wait<0>();                              // B(it), Ai(it+1) done
        __syncthreads();                           // Af(it) visible

        if (it + 1 < NCHUNK) {
            g_convA(sm + AI_BASE + ((it + 1) & 1) * AI_ST,
                    sm + AF_BASE + ((it + 1) & 1) * AF_ST, tid);
            g_cpB(smb + B_BASE + ((it + 1) & 1) * B_ST, k0, it + 1, tid);
            if (it + 2 < NCHUNK)
                g_cpAi(smb + AI_BASE + ((it + 2) & 1) * AI_ST, adj, m0, k0, it + 2, tid);
            cp_commit();
        }

        uint32_t Ab = smb + AF_BASE + (it & 1) * AF_ST;
        uint32_t Bb = smb + B_BASE + (it & 1) * B_ST;
        #pragma unroll
        for (int ks = 0; ks < 4; ks++) {
            uint32_t af[2][4];
            #pragma unroll
            for (int mf = 0; mf < 2; mf++) {
                uint32_t o = swz(a_row0 + mf * 16u, (uint32_t)(ks * 32) + a_kb);
                ldsm_x4(Ab + o, af[mf][0], af[mf][1], af[mf][2], af[mf][3]);
            }
            #pragma unroll
            for (int nf2 = 0; nf2 < 4; nf2++) {
                uint32_t r0, r1, r2, r3;
                uint32_t o = swz(b_row0 + nf2 * 16u, (uint32_t)(ks * 32) + b_kb);
                ldsm_x4(Bb + o, r0, r1, r2, r3);
                #pragma unroll
                for (int mf = 0; mf < 2; mf++) {
                    mma_f16(acc[mf][nf2 * 2 + 0], af[mf], r0, r1);
                    mma_f16(acc[mf][nf2 * 2 + 1], af[mf], r2, r3);
                }
            }
        }
    }

    // write split-K partials
    float* P = g_P + (size_t)kt * NROWS * OUT_F;
    #pragma unroll
    for (int mf = 0; mf < 2; mf++) {
        int r0 = m0 + mw * 32 + mf * 16 + (l >> 2);
        #pragma unroll
        for (int nf = 0; nf < 8; nf++) {
            int col = nw * 64 + nf * 8 + (l & 3) * 2;
            *(float2*)(P + (size_t)r0 * OUT_F + col) =
                make_float2(acc[mf][nf][0], acc[mf][nf][1]);
            *(float2*)(P + (size_t)(r0 + 8) * OUT_F + col) =
                make_float2(acc[mf][nf][2], acc[mf][nf][3]);
        }
    }
}

// ---------------------------------------------------------------------------
// Kernel E: combine split-K partials + epilogue
// ---------------------------------------------------------------------------
__global__ void __launch_bounds__(256) combine_kernel(float* __restrict__ out) {
    size_t idx = (size_t)blockIdx.x * 256 + threadIdx.x;
    int c = (int)(idx & (OUT_F - 1));
    float p = g_P[idx] + g_P[(size_t)NROWS * OUT_F + idx];
    out[idx] = NEGC * (g_S[c] - p);
}

// ---------------------------------------------------------------------------
// Launch
// ---------------------------------------------------------------------------
extern "C" void kernel_launch(void* const* d_in, const int* in_sizes, int n_in,
                              void* d_out, int out_size) {
    const float* x   = (const float*)d_in[0];   // [8192, 512]
    const float* W   = (const float*)d_in[1];   // [512, 256]
    const int*   adj = (const int*)d_in[3];     // [8192, 8192]
    float* out = (float*)d_out;                 // [8192, 256]

    convert_W_kernel<<<512, 256>>>(W);

    cudaFuncSetAttribute(gemm_h_kernel, cudaFuncAttributeMaxDynamicSharedMemorySize, H_SMEM);
    gemm_h_kernel<<<dim3(2, 64), 256, H_SMEM>>>(x);

    reduce_S_kernel<<<1, 256>>>();

    cudaFuncSetAttribute(gat_gemm_kernel, cudaFuncAttributeMaxDynamicSharedMemorySize, GAT_SMEM);
    gat_gemm_kernel<<<dim3(2, NROWS / 64), 256, GAT_SMEM>>>(adj);

    combine_kernel<<<(NROWS * OUT_F) / 256, 256>>>(out);
}